// round 15
// baseline (speedup 1.0000x reference)
#include <cuda_runtime.h>
#include <cuda_fp16.h>
#include <cstdint>

#define N_NODES 50000
#define DIM     512
#define N_EDGES 1600000
#define NBLK    ((N_NODES + 255) / 256)   // 196
#define NSLAB   4
#define SLABW   (DIM / NSLAB)             // 128 cols per slab

// ---------------- scratch (static __device__, no allocation) ----------------
__device__ int    g_counts [N_NODES];
__device__ int    g_offsets[N_NODES + 1];
__device__ int    g_cursor [N_NODES];
__device__ int    g_bsum   [NBLK];
__device__ int    g_boff   [NBLK];
__device__ int    g_src_sorted[N_EDGES];
__device__ float  g_w_sorted  [N_EDGES];
__device__ __half g_xh     [N_NODES * DIM];  // x rounded to fp16      [M, K]
__device__ __half g_Wht    [DIM * DIM];      // W^T in fp16: [n][k]
__device__ __half g_support[N_NODES * DIM];  // x @ W rounded to fp16  [M, N]

// ---------------- helpers ----------------
__device__ __forceinline__ uint32_t smem_u32(const void* p) {
    uint32_t a;
    asm("{ .reg .u64 t; cvta.to.shared.u64 t, %1; cvt.u32.u64 %0, t; }" : "=r"(a) : "l"(p));
    return a;
}
__device__ __forceinline__ void cp16(uint32_t dst, const void* src, uint32_t bytes) {
    asm volatile("cp.async.ca.shared.global [%0], [%1], 16, %2;"
                 :: "r"(dst), "l"(src), "r"(bytes) : "memory");
}
#define CP_COMMIT() asm volatile("cp.async.commit_group;" ::: "memory")
#define CP_WAIT_1() asm volatile("cp.async.wait_group 1;" ::: "memory")
#define CP_WAIT_0() asm volatile("cp.async.wait_group 0;" ::: "memory")

// fp16 MMA, fp32 accumulate: D[16x8] += A[16x16] * B[16x8]
__device__ __forceinline__ void mma_f16(float* c, const uint32_t* a, const uint32_t* b) {
    asm volatile(
        "mma.sync.aligned.m16n8k16.row.col.f32.f16.f16.f32 "
        "{%0,%1,%2,%3}, {%4,%5,%6,%7}, {%8,%9}, {%0,%1,%2,%3};"
        : "+f"(c[0]), "+f"(c[1]), "+f"(c[2]), "+f"(c[3])
        : "r"(a[0]), "r"(a[1]), "r"(a[2]), "r"(a[3]), "r"(b[0]), "r"(b[1]));
}

// ---------------- main branch: CSR build ----------------
__global__ void hist_kernel(const int* __restrict__ dst) {
    int e = blockIdx.x * blockDim.x + threadIdx.x;
    if (e < N_EDGES) atomicAdd(&g_counts[dst[e]], 1);
}

__global__ __launch_bounds__(256) void scan_reduce_kernel() {
    __shared__ int s[256];
    int i = blockIdx.x * 256 + threadIdx.x;
    int v = (i < N_NODES) ? g_counts[i] : 0;
    s[threadIdx.x] = v;
    __syncthreads();
    #pragma unroll
    for (int off = 128; off > 0; off >>= 1) {
        if (threadIdx.x < off) s[threadIdx.x] += s[threadIdx.x + off];
        __syncthreads();
    }
    if (threadIdx.x == 0) g_bsum[blockIdx.x] = s[0];
}

__global__ __launch_bounds__(256) void scan_blocks_kernel() {
    __shared__ int s[256];
    int v = (threadIdx.x < NBLK) ? g_bsum[threadIdx.x] : 0;
    s[threadIdx.x] = v;
    __syncthreads();
    #pragma unroll
    for (int off = 1; off < 256; off <<= 1) {
        int t = (threadIdx.x >= off) ? s[threadIdx.x - off] : 0;
        __syncthreads();
        s[threadIdx.x] += t;
        __syncthreads();
    }
    if (threadIdx.x < NBLK) g_boff[threadIdx.x] = s[threadIdx.x] - v;   // exclusive
    if (threadIdx.x == 255) g_offsets[N_NODES] = s[255];                // total
}

__global__ __launch_bounds__(256) void scan_final_kernel() {
    __shared__ int s[256];
    int i = blockIdx.x * 256 + threadIdx.x;
    int v = (i < N_NODES) ? g_counts[i] : 0;
    s[threadIdx.x] = v;
    __syncthreads();
    #pragma unroll
    for (int off = 1; off < 256; off <<= 1) {
        int t = (threadIdx.x >= off) ? s[threadIdx.x - off] : 0;
        __syncthreads();
        s[threadIdx.x] += t;
        __syncthreads();
    }
    if (i < N_NODES) {
        int pref = s[threadIdx.x] - v + g_boff[blockIdx.x];   // exclusive prefix
        g_offsets[i] = pref;
        g_cursor [i] = pref;
    }
}

__global__ void fill_kernel(const int* __restrict__ src,
                            const int* __restrict__ dst,
                            const float* __restrict__ w) {
    int e = blockIdx.x * blockDim.x + threadIdx.x;
    if (e < N_EDGES) {
        int d   = dst[e];
        int pos = atomicAdd(&g_cursor[d], 1);
        g_src_sorted[pos] = src[e];
        g_w_sorted[pos]   = w[e];
    }
}

// ---------------- side branch: convert x / transpose W / GEMM ----------------
__global__ __launch_bounds__(256) void convert_x_kernel(const float4* __restrict__ X4) {
    int i = blockIdx.x * blockDim.x + threadIdx.x;   // over N*D/8
    float4 v0 = X4[i * 2];
    float4 v1 = X4[i * 2 + 1];
    __half2 h0 = __floats2half2_rn(v0.x, v0.y);
    __half2 h1 = __floats2half2_rn(v0.z, v0.w);
    __half2 h2 = __floats2half2_rn(v1.x, v1.y);
    __half2 h3 = __floats2half2_rn(v1.z, v1.w);
    uint4 o;
    o.x = *reinterpret_cast<uint32_t*>(&h0);
    o.y = *reinterpret_cast<uint32_t*>(&h1);
    o.z = *reinterpret_cast<uint32_t*>(&h2);
    o.w = *reinterpret_cast<uint32_t*>(&h3);
    reinterpret_cast<uint4*>(g_xh)[i] = o;
}

__global__ __launch_bounds__(256) void convert_w_kernel(const float* __restrict__ W) {
    __shared__ float t[32][33];
    int bx = blockIdx.x;   // n tile
    int by = blockIdx.y;   // k tile
    int xn = bx * 32 + threadIdx.x;
    int yk = by * 32 + threadIdx.y;
    #pragma unroll
    for (int j = 0; j < 32; j += 8)
        t[threadIdx.y + j][threadIdx.x] = W[(yk + j) * DIM + xn];
    __syncthreads();
    int xk = by * 32 + threadIdx.x;
    int yn = bx * 32 + threadIdx.y;
    #pragma unroll
    for (int j = 0; j < 32; j += 8)
        g_Wht[(yn + j) * DIM + xk] = __float2half_rn(t[threadIdx.x][threadIdx.y + j]);
}

// support[:, nBase:nBase+128] = fp16(x) @ fp16(W) slab
#define BM 128
#define BN 128
#define BK 32
#define NKI (DIM / BK)          // 16
#define STRIDE_H 40
#define SA_H (BM * STRIDE_H)
#define SB_H (BN * STRIDE_H)
#define SMEM_BYTES (2 * (SA_H + SB_H) * 2)   // 40960

__device__ __forceinline__ void stage_tiles_f16(
    uint32_t saA, uint32_t saB, int mBase, int nBase, int k0, int tid)
{
    #pragma unroll
    for (int p = 0; p < 2; ++p) {
        int c    = p * 256 + tid;
        int row  = c >> 2;
        int ch   = c & 3;
        int grow = mBase + row;
        int ok   = (grow < N_NODES);
        const __half* src = g_xh + (size_t)(ok ? grow : 0) * DIM + k0 + ch * 8;
        cp16(saA + (uint32_t)(row * STRIDE_H + ch * 8) * 2, src, ok ? 16u : 0u);
    }
    #pragma unroll
    for (int p = 0; p < 2; ++p) {
        int c   = p * 256 + tid;
        int row = c >> 2;
        int ch  = c & 3;
        const __half* src = g_Wht + (size_t)(nBase + row) * DIM + k0 + ch * 8;
        cp16(saB + (uint32_t)(row * STRIDE_H + ch * 8) * 2, src, 16u);
    }
}

__global__ __launch_bounds__(256, 2) void mma_gemm_kernel(
    __half* __restrict__ sup, int nBase)
{
    extern __shared__ __half smh[];
    const uint32_t sb = smem_u32(smh);
    const uint32_t SA[2] = { sb, sb + SA_H * 2 };
    const uint32_t SB[2] = { sb + 2 * SA_H * 2, sb + 2 * SA_H * 2 + SB_H * 2 };

    const int tid  = threadIdx.x;
    const int wid  = tid >> 5;
    const int lane = tid & 31;
    const int gid  = lane >> 2;
    const int tig  = lane & 3;
    const int wm   = wid & 3;
    const int wn   = wid >> 2;

    const int mBase = blockIdx.x * BM;

    float acc[2][8][4];
    #pragma unroll
    for (int i = 0; i < 2; ++i)
        #pragma unroll
        for (int j = 0; j < 8; ++j)
            #pragma unroll
            for (int q = 0; q < 4; ++q) acc[i][j][q] = 0.f;

    stage_tiles_f16(SA[0], SB[0], mBase, nBase, 0, tid);
    CP_COMMIT();

    int buf = 0;
    for (int it = 0; it < NKI; ++it) {
        if (it + 1 < NKI) {
            stage_tiles_f16(SA[buf ^ 1], SB[buf ^ 1], mBase, nBase, (it + 1) * BK, tid);
            CP_COMMIT();
            CP_WAIT_1();
        } else {
            CP_WAIT_0();
        }
        __syncthreads();

        const __half* As = smh + (buf ? SA_H : 0);
        const __half* Bs = smh + 2 * SA_H + (buf ? SB_H : 0);

        #pragma unroll
        for (int ks = 0; ks < 2; ++ks) {
            const int kk = ks * 16;
            uint32_t a[2][4];
            #pragma unroll
            for (int i = 0; i < 2; ++i) {
                int r0 = wm * 32 + i * 16 + gid;
                a[i][0] = *reinterpret_cast<const uint32_t*>(&As[(r0    ) * STRIDE_H + kk     + tig * 2]);
                a[i][1] = *reinterpret_cast<const uint32_t*>(&As[(r0 + 8) * STRIDE_H + kk     + tig * 2]);
                a[i][2] = *reinterpret_cast<const uint32_t*>(&As[(r0    ) * STRIDE_H + kk + 8 + tig * 2]);
                a[i][3] = *reinterpret_cast<const uint32_t*>(&As[(r0 + 8) * STRIDE_H + kk + 8 + tig * 2]);
            }
            uint32_t b[8][2];
            #pragma unroll
            for (int j = 0; j < 8; ++j) {
                int n0 = wn * 64 + j * 8 + gid;
                b[j][0] = *reinterpret_cast<const uint32_t*>(&Bs[n0 * STRIDE_H + kk     + tig * 2]);
                b[j][1] = *reinterpret_cast<const uint32_t*>(&Bs[n0 * STRIDE_H + kk + 8 + tig * 2]);
            }
            #pragma unroll
            for (int i = 0; i < 2; ++i)
                #pragma unroll
                for (int j = 0; j < 8; ++j)
                    mma_f16(acc[i][j], a[i], b[j]);
        }
        __syncthreads();
        buf ^= 1;
    }

    #pragma unroll
    for (int i = 0; i < 2; ++i) {
        int r0 = mBase + wm * 32 + i * 16 + gid;
        int r1 = r0 + 8;
        #pragma unroll
        for (int j = 0; j < 8; ++j) {
            int col = nBase + wn * 64 + j * 8 + tig * 2;
            if (r0 < N_NODES) {
                __half2 h = __floats2half2_rn(acc[i][j][0], acc[i][j][1]);
                *reinterpret_cast<__half2*>(&sup[(size_t)r0 * DIM + col]) = h;
            }
            if (r1 < N_NODES) {
                __half2 h = __floats2half2_rn(acc[i][j][2], acc[i][j][3]);
                *reinterpret_cast<__half2*>(&sup[(size_t)r1 * DIM + col]) = h;
            }
        }
    }
}

// ---------------- fused tail: per-slab fp16 gather + bias + relu + residual ----
// warp-per-node, 4 warps/CTA; lane owns 4 cols (one uint2) of this 128-col slab.
__global__ __launch_bounds__(128) void aggregate_slab_kernel(
    const uint2*  __restrict__ sup2,   // g_support as uint2 [M * 128]
    const float4* __restrict__ x4,     // x as float4
    const float4* __restrict__ bias4,  // bias as float4 [128]
    float4* __restrict__ out4,         // output as float4
    int colBase)                       // slab start col (halfs): 0,128,256,384
{
    const int warp = threadIdx.x >> 5;
    const int lane = threadIdx.x & 31;
    const int n    = blockIdx.x * 4 + warp;
    if (n >= N_NODES) return;

    const int beg = g_offsets[n];
    const int end = g_offsets[n + 1];
    const int cb4 = colBase >> 2;              // offset in uint2/float4 units
    const uint2* supS = sup2 + cb4 + lane;     // row stride stays 128 uint2

    float4 acc0 = make_float4(0.f, 0.f, 0.f, 0.f);
    float4 acc1 = make_float4(0.f, 0.f, 0.f, 0.f);

    int e = beg;
    for (; e + 1 < end; e += 2) {
        int   s0 = g_src_sorted[e];
        int   s1 = g_src_sorted[e + 1];
        float w0 = g_w_sorted[e];
        float w1 = g_w_sorted[e + 1];
        uint2 u0 = supS[s0 * 128];
        uint2 u1 = supS[s1 * 128];
        float2 p00 = __half22float2(*reinterpret_cast<__half2*>(&u0.x));
        float2 p01 = __half22float2(*reinterpret_cast<__half2*>(&u0.y));
        float2 p10 = __half22float2(*reinterpret_cast<__half2*>(&u1.x));
        float2 p11 = __half22float2(*reinterpret_cast<__half2*>(&u1.y));
        acc0.x += w0 * p00.x;  acc0.y += w0 * p00.y;
        acc0.z += w0 * p01.x;  acc0.w += w0 * p01.y;
        acc1.x += w1 * p10.x;  acc1.y += w1 * p10.y;
        acc1.z += w1 * p11.x;  acc1.w += w1 * p11.y;
    }
    if (e < end) {
        int   s0 = g_src_sorted[e];
        float w0 = g_w_sorted[e];
        uint2 u0 = supS[s0 * 128];
        float2 p00 = __half22float2(*reinterpret_cast<__half2*>(&u0.x));
        float2 p01 = __half22float2(*reinterpret_cast<__half2*>(&u0.y));
        acc0.x += w0 * p00.x;  acc0.y += w0 * p00.y;
        acc0.z += w0 * p01.x;  acc0.w += w0 * p01.y;
    }
    acc0.x += acc1.x; acc0.y += acc1.y; acc0.z += acc1.z; acc0.w += acc1.w;

    float4 bb = bias4[cb4 + lane];
    float4 xr = x4[n * 128 + cb4 + lane];
    float4 o;
    o.x = fmaxf(acc0.x + bb.x, 0.f) + xr.x;
    o.y = fmaxf(acc0.y + bb.y, 0.f) + xr.y;
    o.z = fmaxf(acc0.z + bb.z, 0.f) + xr.z;
    o.w = fmaxf(acc0.w + bb.w, 0.f) + xr.w;
    out4[n * 128 + cb4 + lane] = o;
}

// ---------------- launch ----------------
extern "C" void kernel_launch(void* const* d_in, const int* in_sizes, int n_in,
                              void* d_out, int out_size) {
    const float* x    = (const float*)d_in[0];  // [N, D]
    const float* W    = (const float*)d_in[1];  // [D, D]
    const float* b    = (const float*)d_in[2];  // [D]
    const float* ew   = (const float*)d_in[3];  // [E]
    const int*   esrc = (const int*)  d_in[4];  // [E]
    const int*   edst = (const int*)  d_in[5];  // [E]
    float* out = (float*)d_out;

    __half* sup_ptr;    cudaGetSymbolAddress((void**)&sup_ptr, g_support);
    int*    counts_ptr; cudaGetSymbolAddress((void**)&counts_ptr, g_counts);

    cudaFuncSetAttribute(mma_gemm_kernel,
                         cudaFuncAttributeMaxDynamicSharedMemorySize, SMEM_BYTES);

    // fork a side branch for the dense GEMM (independent of CSR build).
    // streams/events created per call, intentionally not destroyed
    // (destroy during active capture is illegal; kernel_launch runs twice).
    cudaStream_t s1;
    cudaStreamCreateWithFlags(&s1, cudaStreamNonBlocking);
    cudaEvent_t evFork;
    cudaEventCreateWithFlags(&evFork, cudaEventDisableTiming);
    cudaEvent_t evG[NSLAB];
    for (int s = 0; s < NSLAB; ++s)
        cudaEventCreateWithFlags(&evG[s], cudaEventDisableTiming);

    cudaEventRecord(evFork, 0);
    cudaStreamWaitEvent(s1, evFork, 0);

    // side branch: x->fp16, W->fp16 transposed, then 4 GEMM column slabs
    convert_x_kernel<<<(N_NODES * DIM / 8) / 256, 256, 0, s1>>>(
        reinterpret_cast<const float4*>(x));
    convert_w_kernel<<<dim3(DIM / 32, DIM / 32), dim3(32, 8), 0, s1>>>(W);
    for (int s = 0; s < NSLAB; ++s) {
        mma_gemm_kernel<<<(N_NODES + BM - 1) / BM, 256, SMEM_BYTES, s1>>>(
            sup_ptr, s * SLABW);
        cudaEventRecord(evG[s], s1);
    }

    // main branch: CSR build
    cudaMemsetAsync(counts_ptr, 0, N_NODES * sizeof(int), 0);
    hist_kernel<<<N_EDGES / 256, 256>>>(edst);
    scan_reduce_kernel<<<NBLK, 256>>>();
    scan_blocks_kernel<<<1, 256>>>();
    scan_final_kernel<<<NBLK, 256>>>();
    fill_kernel<<<N_EDGES / 256, 256>>>(esrc, edst, ew);

    // pipelined joins: each aggregate slab waits only on its GEMM slab
    for (int s = 0; s < NSLAB; ++s) {
        cudaStreamWaitEvent(0, evG[s], 0);
        aggregate_slab_kernel<<<(N_NODES + 3) / 4, 128>>>(
            reinterpret_cast<const uint2*>(sup_ptr),
            reinterpret_cast<const float4*>(x),
            reinterpret_cast<const float4*>(b),
            reinterpret_cast<float4*>(out),
            s * SLABW);
    }
}

// round 16
// speedup vs baseline: 1.1017x; 1.1017x over previous
#include <cuda_runtime.h>
#include <cuda_fp16.h>
#include <cstdint>

#define N_NODES 50000
#define DIM     512
#define N_EDGES 1600000
#define NBLK    ((N_NODES + 255) / 256)   // 196

// ---------------- scratch (static __device__, no allocation) ----------------
__device__ int    g_counts [N_NODES];
__device__ int    g_offsets[N_NODES + 1];
__device__ int    g_cursor [N_NODES];
__device__ int    g_bsum   [NBLK];
__device__ int    g_boff   [NBLK];
__device__ int    g_src_sorted[N_EDGES];
__device__ float  g_w_sorted  [N_EDGES];
__device__ __half g_xh     [N_NODES * DIM];  // x rounded to fp16      [M, K]
__device__ __half g_Wht    [DIM * DIM];      // W^T in fp16: [n][k]
__device__ __half g_support[N_NODES * DIM];  // x @ W rounded to fp16  [M, N]

// ---------------- helpers ----------------
__device__ __forceinline__ uint32_t smem_u32(const void* p) {
    uint32_t a;
    asm("{ .reg .u64 t; cvta.to.shared.u64 t, %1; cvt.u32.u64 %0, t; }" : "=r"(a) : "l"(p));
    return a;
}
__device__ __forceinline__ void cp16(uint32_t dst, const void* src, uint32_t bytes) {
    asm volatile("cp.async.ca.shared.global [%0], [%1], 16, %2;"
                 :: "r"(dst), "l"(src), "r"(bytes) : "memory");
}
#define CP_COMMIT() asm volatile("cp.async.commit_group;" ::: "memory")
#define CP_WAIT_1() asm volatile("cp.async.wait_group 1;" ::: "memory")
#define CP_WAIT_0() asm volatile("cp.async.wait_group 0;" ::: "memory")

// fp16 MMA, fp32 accumulate: D[16x8] += A[16x16] * B[16x8]
__device__ __forceinline__ void mma_f16(float* c, const uint32_t* a, const uint32_t* b) {
    asm volatile(
        "mma.sync.aligned.m16n8k16.row.col.f32.f16.f16.f32 "
        "{%0,%1,%2,%3}, {%4,%5,%6,%7}, {%8,%9}, {%0,%1,%2,%3};"
        : "+f"(c[0]), "+f"(c[1]), "+f"(c[2]), "+f"(c[3])
        : "r"(a[0]), "r"(a[1]), "r"(a[2]), "r"(a[3]), "r"(b[0]), "r"(b[1]));
}

__device__ __forceinline__ void ldmatrix_x4(uint32_t& d0, uint32_t& d1,
                                            uint32_t& d2, uint32_t& d3, uint32_t addr) {
    asm volatile("ldmatrix.sync.aligned.m8n8.x4.shared.b16 {%0,%1,%2,%3}, [%4];"
                 : "=r"(d0), "=r"(d1), "=r"(d2), "=r"(d3) : "r"(addr));
}

// ---------------- main branch: CSR build ----------------
__global__ void hist_kernel(const int* __restrict__ dst) {
    int e = blockIdx.x * blockDim.x + threadIdx.x;
    if (e < N_EDGES) atomicAdd(&g_counts[dst[e]], 1);
}

__global__ __launch_bounds__(256) void scan_reduce_kernel() {
    __shared__ int s[256];
    int i = blockIdx.x * 256 + threadIdx.x;
    int v = (i < N_NODES) ? g_counts[i] : 0;
    s[threadIdx.x] = v;
    __syncthreads();
    #pragma unroll
    for (int off = 128; off > 0; off >>= 1) {
        if (threadIdx.x < off) s[threadIdx.x] += s[threadIdx.x + off];
        __syncthreads();
    }
    if (threadIdx.x == 0) g_bsum[blockIdx.x] = s[0];
}

__global__ __launch_bounds__(256) void scan_blocks_kernel() {
    __shared__ int s[256];
    int v = (threadIdx.x < NBLK) ? g_bsum[threadIdx.x] : 0;
    s[threadIdx.x] = v;
    __syncthreads();
    #pragma unroll
    for (int off = 1; off < 256; off <<= 1) {
        int t = (threadIdx.x >= off) ? s[threadIdx.x - off] : 0;
        __syncthreads();
        s[threadIdx.x] += t;
        __syncthreads();
    }
    if (threadIdx.x < NBLK) g_boff[threadIdx.x] = s[threadIdx.x] - v;   // exclusive
    if (threadIdx.x == 255) g_offsets[N_NODES] = s[255];                // total
}

__global__ __launch_bounds__(256) void scan_final_kernel() {
    __shared__ int s[256];
    int i = blockIdx.x * 256 + threadIdx.x;
    int v = (i < N_NODES) ? g_counts[i] : 0;
    s[threadIdx.x] = v;
    __syncthreads();
    #pragma unroll
    for (int off = 1; off < 256; off <<= 1) {
        int t = (threadIdx.x >= off) ? s[threadIdx.x - off] : 0;
        __syncthreads();
        s[threadIdx.x] += t;
        __syncthreads();
    }
    if (i < N_NODES) {
        int pref = s[threadIdx.x] - v + g_boff[blockIdx.x];   // exclusive prefix
        g_offsets[i] = pref;
        g_cursor [i] = pref;
    }
}

__global__ void fill_kernel(const int* __restrict__ src,
                            const int* __restrict__ dst,
                            const float* __restrict__ w) {
    int e = blockIdx.x * blockDim.x + threadIdx.x;
    if (e < N_EDGES) {
        int d   = dst[e];
        int pos = atomicAdd(&g_cursor[d], 1);
        g_src_sorted[pos] = src[e];
        g_w_sorted[pos]   = w[e];
    }
}

// ---------------- side branch: convert x / transpose W / GEMM ----------------
__global__ __launch_bounds__(256) void convert_x_kernel(const float4* __restrict__ X4) {
    int i = blockIdx.x * blockDim.x + threadIdx.x;   // over N*D/8
    float4 v0 = X4[i * 2];
    float4 v1 = X4[i * 2 + 1];
    __half2 h0 = __floats2half2_rn(v0.x, v0.y);
    __half2 h1 = __floats2half2_rn(v0.z, v0.w);
    __half2 h2 = __floats2half2_rn(v1.x, v1.y);
    __half2 h3 = __floats2half2_rn(v1.z, v1.w);
    uint4 o;
    o.x = *reinterpret_cast<uint32_t*>(&h0);
    o.y = *reinterpret_cast<uint32_t*>(&h1);
    o.z = *reinterpret_cast<uint32_t*>(&h2);
    o.w = *reinterpret_cast<uint32_t*>(&h3);
    reinterpret_cast<uint4*>(g_xh)[i] = o;
}

__global__ __launch_bounds__(256) void convert_w_kernel(const float* __restrict__ W) {
    __shared__ float t[32][33];
    int bx = blockIdx.x;   // n tile
    int by = blockIdx.y;   // k tile
    int xn = bx * 32 + threadIdx.x;
    int yk = by * 32 + threadIdx.y;
    #pragma unroll
    for (int j = 0; j < 32; j += 8)
        t[threadIdx.y + j][threadIdx.x] = W[(yk + j) * DIM + xn];
    __syncthreads();
    int xk = by * 32 + threadIdx.x;
    int yn = bx * 32 + threadIdx.y;
    #pragma unroll
    for (int j = 0; j < 32; j += 8)
        g_Wht[(yn + j) * DIM + xk] = __float2half_rn(t[threadIdx.x][threadIdx.y + j]);
}

// support = fp16(x) @ fp16(W)  (fp32 accum, fp16 store)
// BM=128 BN=128 BK=32; 8 warps (4 M x 2 N), warp tile 32x64, m16n8k16, ldmatrix.
#define BM 128
#define BN 128
#define BK 32
#define NKI (DIM / BK)          // 16
#define STRIDE_H 40             // 32 halfs + pad: 80B rows, ldmatrix conflict-free
#define SA_H (BM * STRIDE_H)
#define SB_H (BN * STRIDE_H)
#define SMEM_BYTES (2 * (SA_H + SB_H) * 2)   // 40960

__device__ __forceinline__ void stage_tiles_f16(
    uint32_t saA, uint32_t saB, int mBase, int nBase, int k0, int tid)
{
    #pragma unroll
    for (int p = 0; p < 2; ++p) {
        int c    = p * 256 + tid;
        int row  = c >> 2;
        int ch   = c & 3;
        int grow = mBase + row;
        int ok   = (grow < N_NODES);
        const __half* src = g_xh + (size_t)(ok ? grow : 0) * DIM + k0 + ch * 8;
        cp16(saA + (uint32_t)(row * STRIDE_H + ch * 8) * 2, src, ok ? 16u : 0u);
    }
    #pragma unroll
    for (int p = 0; p < 2; ++p) {
        int c   = p * 256 + tid;
        int row = c >> 2;
        int ch  = c & 3;
        const __half* src = g_Wht + (size_t)(nBase + row) * DIM + k0 + ch * 8;
        cp16(saB + (uint32_t)(row * STRIDE_H + ch * 8) * 2, src, 16u);
    }
}

__global__ __launch_bounds__(256, 2) void mma_gemm_kernel(
    __half* __restrict__ sup)        // g_support [M, N] fp16
{
    extern __shared__ __half smh[];
    const uint32_t sb = smem_u32(smh);
    const uint32_t SA[2] = { sb, sb + SA_H * 2 };
    const uint32_t SB[2] = { sb + 2 * SA_H * 2, sb + 2 * SA_H * 2 + SB_H * 2 };

    const int tid  = threadIdx.x;
    const int wid  = tid >> 5;
    const int lane = tid & 31;
    const int gid  = lane >> 2;
    const int tig  = lane & 3;
    const int wm   = wid & 3;
    const int wn   = wid >> 2;

    const int mBase = blockIdx.y * BM;
    const int nBase = blockIdx.x * BN;

    // per-lane ldmatrix base offsets (bytes), k=0
    // A (.x4): lanes 0-15 -> row (r0+lane, col kk); lanes 16-31 -> (r0+lane-16, kk+8)
    const uint32_t aOff = (uint32_t)(((wm * 32 + (lane & 15)) * STRIDE_H
                                      + ((lane >> 4) << 3)) * 2);
    // B (.x4, pair j,j+1): groups -> (n_j+l,kk),(n_j+l,kk+8),(n_j+8+l,kk),(n_j+8+l,kk+8)
    const uint32_t bOff = (uint32_t)(((wn * 64 + (lane & 7) + ((lane >> 4) << 3)) * STRIDE_H
                                      + (((lane >> 3) & 1) << 3)) * 2);

    float acc[2][8][4];
    #pragma unroll
    for (int i = 0; i < 2; ++i)
        #pragma unroll
        for (int j = 0; j < 8; ++j)
            #pragma unroll
            for (int q = 0; q < 4; ++q) acc[i][j][q] = 0.f;

    stage_tiles_f16(SA[0], SB[0], mBase, nBase, 0, tid);
    CP_COMMIT();

    int buf = 0;
    for (int it = 0; it < NKI; ++it) {
        if (it + 1 < NKI) {
            stage_tiles_f16(SA[buf ^ 1], SB[buf ^ 1], mBase, nBase, (it + 1) * BK, tid);
            CP_COMMIT();
            CP_WAIT_1();
        } else {
            CP_WAIT_0();
        }
        __syncthreads();

        const uint32_t aSm = SA[buf];
        const uint32_t bSm = SB[buf];

        #pragma unroll
        for (int ks = 0; ks < 2; ++ks) {
            const uint32_t kByte = (uint32_t)(ks * 16 * 2);   // kk halfs -> bytes
            uint32_t a[2][4];
            #pragma unroll
            for (int i = 0; i < 2; ++i)
                ldmatrix_x4(a[i][0], a[i][1], a[i][2], a[i][3],
                            aSm + aOff + (uint32_t)(i * 16 * STRIDE_H * 2) + kByte);
            uint32_t b[8][2];
            #pragma unroll
            for (int j2 = 0; j2 < 4; ++j2)
                ldmatrix_x4(b[2 * j2][0], b[2 * j2][1], b[2 * j2 + 1][0], b[2 * j2 + 1][1],
                            bSm + bOff + (uint32_t)(j2 * 16 * STRIDE_H * 2) + kByte);
            #pragma unroll
            for (int i = 0; i < 2; ++i)
                #pragma unroll
                for (int j = 0; j < 8; ++j)
                    mma_f16(acc[i][j], a[i], b[j]);
        }
        __syncthreads();
        buf ^= 1;
    }

    // epilogue: pack float2 -> half2 (cols tig*2, tig*2+1 adjacent & even)
    #pragma unroll
    for (int i = 0; i < 2; ++i) {
        int r0 = mBase + wm * 32 + i * 16 + gid;
        int r1 = r0 + 8;
        #pragma unroll
        for (int j = 0; j < 8; ++j) {
            int col = nBase + wn * 64 + j * 8 + tig * 2;
            if (r0 < N_NODES) {
                __half2 h = __floats2half2_rn(acc[i][j][0], acc[i][j][1]);
                *reinterpret_cast<__half2*>(&sup[(size_t)r0 * DIM + col]) = h;
            }
            if (r1 < N_NODES) {
                __half2 h = __floats2half2_rn(acc[i][j][2], acc[i][j][3]);
                *reinterpret_cast<__half2*>(&sup[(size_t)r1 * DIM + col]) = h;
            }
        }
    }
}

// ---------------- fused tail: fp16 gather + bias + relu + residual ----------------
// one CTA (128 threads) per node; 2 edges in flight (R8: wider regresses)
__global__ __launch_bounds__(128) void aggregate_fused_kernel(
    const uint2*  __restrict__ sup2,   // g_support as uint2 [M * 128]
    const float4* __restrict__ x4,     // x as float4
    const float4* __restrict__ bias4,  // bias as float4 [128]
    float4* __restrict__ out4)         // output as float4
{
    const int n   = blockIdx.x;
    const int tid = threadIdx.x;
    const int beg = g_offsets[n];
    const int end = g_offsets[n + 1];

    float4 acc0 = make_float4(0.f, 0.f, 0.f, 0.f);
    float4 acc1 = make_float4(0.f, 0.f, 0.f, 0.f);

    int e = beg;
    for (; e + 1 < end; e += 2) {
        int   s0 = g_src_sorted[e];
        int   s1 = g_src_sorted[e + 1];
        float w0 = g_w_sorted[e];
        float w1 = g_w_sorted[e + 1];
        uint2 u0 = sup2[s0 * 128 + tid];
        uint2 u1 = sup2[s1 * 128 + tid];
        float2 p00 = __half22float2(*reinterpret_cast<__half2*>(&u0.x));
        float2 p01 = __half22float2(*reinterpret_cast<__half2*>(&u0.y));
        float2 p10 = __half22float2(*reinterpret_cast<__half2*>(&u1.x));
        float2 p11 = __half22float2(*reinterpret_cast<__half2*>(&u1.y));
        acc0.x += w0 * p00.x;  acc0.y += w0 * p00.y;
        acc0.z += w0 * p01.x;  acc0.w += w0 * p01.y;
        acc1.x += w1 * p10.x;  acc1.y += w1 * p10.y;
        acc1.z += w1 * p11.x;  acc1.w += w1 * p11.y;
    }
    if (e < end) {
        int   s0 = g_src_sorted[e];
        float w0 = g_w_sorted[e];
        uint2 u0 = sup2[s0 * 128 + tid];
        float2 p00 = __half22float2(*reinterpret_cast<__half2*>(&u0.x));
        float2 p01 = __half22float2(*reinterpret_cast<__half2*>(&u0.y));
        acc0.x += w0 * p00.x;  acc0.y += w0 * p00.y;
        acc0.z += w0 * p01.x;  acc0.w += w0 * p01.y;
    }
    acc0.x += acc1.x; acc0.y += acc1.y; acc0.z += acc1.z; acc0.w += acc1.w;

    float4 bb = bias4[tid];
    float4 xr = x4[n * 128 + tid];
    float4 o;
    o.x = fmaxf(acc0.x + bb.x, 0.f) + xr.x;
    o.y = fmaxf(acc0.y + bb.y, 0.f) + xr.y;
    o.z = fmaxf(acc0.z + bb.z, 0.f) + xr.z;
    o.w = fmaxf(acc0.w + bb.w, 0.f) + xr.w;
    out4[n * 128 + tid] = o;
}

// ---------------- launch ----------------
extern "C" void kernel_launch(void* const* d_in, const int* in_sizes, int n_in,
                              void* d_out, int out_size) {
    const float* x    = (const float*)d_in[0];  // [N, D]
    const float* W    = (const float*)d_in[1];  // [D, D]
    const float* b    = (const float*)d_in[2];  // [D]
    const float* ew   = (const float*)d_in[3];  // [E]
    const int*   esrc = (const int*)  d_in[4];  // [E]
    const int*   edst = (const int*)  d_in[5];  // [E]
    float* out = (float*)d_out;

    __half* sup_ptr;    cudaGetSymbolAddress((void**)&sup_ptr, g_support);
    int*    counts_ptr; cudaGetSymbolAddress((void**)&counts_ptr, g_counts);

    cudaFuncSetAttribute(mma_gemm_kernel,
                         cudaFuncAttributeMaxDynamicSharedMemorySize, SMEM_BYTES);

    // fork a side branch for the dense GEMM (independent of CSR build).
    // streams/events created per call, intentionally not destroyed
    // (destroy during active capture is illegal; kernel_launch runs twice).
    cudaStream_t s1;
    cudaStreamCreateWithFlags(&s1, cudaStreamNonBlocking);
    cudaEvent_t evFork, evJoin;
    cudaEventCreateWithFlags(&evFork, cudaEventDisableTiming);
    cudaEventCreateWithFlags(&evJoin, cudaEventDisableTiming);

    cudaEventRecord(evFork, 0);
    cudaStreamWaitEvent(s1, evFork, 0);

    // side branch: x->fp16, W->fp16 transposed, GEMM
    convert_x_kernel<<<(N_NODES * DIM / 8) / 256, 256, 0, s1>>>(
        reinterpret_cast<const float4*>(x));
    convert_w_kernel<<<dim3(DIM / 32, DIM / 32), dim3(32, 8), 0, s1>>>(W);
    {
        dim3 ggrid(DIM / BN, (N_NODES + BM - 1) / BM);
        mma_gemm_kernel<<<ggrid, 256, SMEM_BYTES, s1>>>(sup_ptr);
    }
    cudaEventRecord(evJoin, s1);

    // main branch: CSR build
    cudaMemsetAsync(counts_ptr, 0, N_NODES * sizeof(int), 0);
    hist_kernel<<<N_EDGES / 256, 256>>>(edst);
    scan_reduce_kernel<<<NBLK, 256>>>();
    scan_blocks_kernel<<<1, 256>>>();
    scan_final_kernel<<<NBLK, 256>>>();
    fill_kernel<<<N_EDGES / 256, 256>>>(esrc, edst, ew);

    // join, then fused fp16 gather + epilogue
    cudaStreamWaitEvent(0, evJoin, 0);
    aggregate_fused_kernel<<<N_NODES, 128>>>(
        reinterpret_cast<const uint2*>(sup_ptr),
        reinterpret_cast<const float4*>(x),
        reinterpret_cast<const float4*>(b),
        reinterpret_cast<float4*>(out));
}